// round 2
// baseline (speedup 1.0000x reference)
#include <cuda_runtime.h>
#include <math.h>
#include <stdint.h>

// Problem constants
#define B 16
#define S 2048
#define M 4
#define E 128
#define HH 128
#define VOCAB 100000
#define NE 4000
#define NR 200
#define FULLMASK 0xffffffffu

// ---------------- device scratch (no allocation allowed) ----------------
__device__ float g_h[B * HH];
__device__ float g_u[B * HH];
__device__ float g_logit[B * S];
__device__ float g_emb1[(size_t)B * S * E];   // summed C1 embeddings per (b,s)
__device__ float g_emb2[(size_t)B * S * E];   // summed C2 embeddings per (b,s)

// ---------------- threefry2x32-20 (JAX) ----------------
__host__ __device__ __forceinline__ uint32_t rotl32(uint32_t v, int d) {
    return (v << d) | (v >> (32 - d));
}

__host__ __device__ __forceinline__ void threefry2x32(
    uint32_t k0, uint32_t k1, uint32_t x0, uint32_t x1,
    uint32_t& o0, uint32_t& o1)
{
    uint32_t ks0 = k0, ks1 = k1;
    uint32_t ks2 = k0 ^ k1 ^ 0x1BD11BDAu;
    x0 += ks0; x1 += ks1;
    const int rA[4] = {13, 15, 26, 6};
    const int rB[4] = {17, 29, 16, 24};
    #pragma unroll
    for (int i = 0; i < 4; i++) { x0 += x1; x1 = rotl32(x1, rA[i]); x1 ^= x0; }
    x0 += ks1; x1 += ks2 + 1u;
    #pragma unroll
    for (int i = 0; i < 4; i++) { x0 += x1; x1 = rotl32(x1, rB[i]); x1 ^= x0; }
    x0 += ks2; x1 += ks0 + 2u;
    #pragma unroll
    for (int i = 0; i < 4; i++) { x0 += x1; x1 = rotl32(x1, rA[i]); x1 ^= x0; }
    x0 += ks0; x1 += ks1 + 3u;
    #pragma unroll
    for (int i = 0; i < 4; i++) { x0 += x1; x1 = rotl32(x1, rB[i]); x1 ^= x0; }
    x0 += ks1; x1 += ks2 + 4u;
    #pragma unroll
    for (int i = 0; i < 4; i++) { x0 += x1; x1 = rotl32(x1, rA[i]); x1 ^= x0; }
    x0 += ks2; x1 += ks0 + 5u;
    o0 = x0; o1 = x1;
}

// ---------------- h = hidden @ Wm^T + Wb ; u = h ----------------
__global__ void k_h(const float* __restrict__ hidden,
                    const float* __restrict__ Wm,
                    const float* __restrict__ Wb)
{
    int b = blockIdx.x, t = threadIdx.x;
    __shared__ float sh[HH];
    sh[t] = hidden[b * HH + t];
    __syncthreads();
    float acc = Wb[t];
    const float* w = Wm + (size_t)t * HH;
    #pragma unroll 8
    for (int k = 0; k < HH; k++) acc = fmaf(w[k], sh[k], acc);
    g_h[b * HH + t] = acc;
    g_u[b * HH + t] = acc;
}

// ---------------- all three head GEMVs: warp per output column n ----------------
__global__ void k_head_all(const float* __restrict__ W1w, const float* __restrict__ W1b,
                           const float* __restrict__ W3w, const float* __restrict__ W3b,
                           const float* __restrict__ W4w, const float* __restrict__ W4b,
                           float* __restrict__ o_sp, float* __restrict__ o_qh,
                           float* __restrict__ o_qt)
{
    int gid  = blockIdx.x * blockDim.x + threadIdx.x;
    int w    = gid >> 5, lane = gid & 31;
    if (w >= 2 + NE + NR) return;
    const float *W, *bias; float* outl; int N, n;
    if (w < 2)            { W = W1w; bias = W1b; outl = o_sp; N = 2;  n = w; }
    else if (w < 2 + NE)  { W = W3w; bias = W3b; outl = o_qh; N = NE; n = w - 2; }
    else                  { W = W4w; bias = W4b; outl = o_qt; N = NR; n = w - 2 - NE; }

    float4 w4 = __ldg((const float4*)(W + (size_t)n * HH) + lane);
    float  bs = __ldg(bias + n);
    #pragma unroll
    for (int b = 0; b < B; b++) {
        float4 h4 = *((const float4*)(g_h + b * HH) + lane);
        float s = w4.x * h4.x + w4.y * h4.y + w4.z * h4.z + w4.w * h4.w;
        #pragma unroll
        for (int o = 16; o; o >>= 1) s += __shfl_down_sync(FULLMASK, s, o);
        if (lane == 0) outl[b * N + n] = s + bs;
    }
}

// ---------------- gumbel noise + argmax + one-hot, one block per (b, head) ----------------
__global__ void k_argmax_all(const float* __restrict__ o_sp, const float* __restrict__ o_qh,
                             const float* __restrict__ o_qt,
                             float* __restrict__ a_sp, float* __restrict__ a_qh,
                             float* __restrict__ a_qt,
                             uint32_t k1a, uint32_t k1b, uint32_t k2a, uint32_t k2b,
                             uint32_t k3a, uint32_t k3b)
{
    int b = blockIdx.x, head = blockIdx.y, t = threadIdx.x;
    const float* L; float* A; int N; uint32_t ka, kb;
    if (head == 0)      { L = o_sp; A = a_sp; N = 2;  ka = k1a; kb = k1b; }
    else if (head == 1) { L = o_qh; A = a_qh; N = NE; ka = k2a; kb = k2b; }
    else                { L = o_qt; A = a_qt; N = NR; ka = k3a; kb = k3b; }

    float bv = -INFINITY; int bi = 0x7fffffff;
    for (int i = t; i < N; i += 256) {
        int idx = b * N + i;
        float logit = __ldg(L + idx);
        uint32_t o0, o1;
        threefry2x32(ka, kb, 0u, (uint32_t)idx, o0, o1);
        uint32_t bits = o0 ^ o1;
        float u = __uint_as_float((bits >> 9) | 0x3F800000u) - 1.0f;
        float v = fmaxf(1e-10f, u + 1e-10f);
        float g = -logf(-logf(v));
        float nv = logit + g;
        if (nv > bv || (nv == bv && i < bi)) { bv = nv; bi = i; }
    }
    __shared__ float sv[256];
    __shared__ int   si[256];
    sv[t] = bv; si[t] = bi;
    __syncthreads();
    for (int o = 128; o; o >>= 1) {
        if (t < o) {
            if (sv[t + o] > sv[t] || (sv[t + o] == sv[t] && si[t + o] < si[t])) {
                sv[t] = sv[t + o]; si[t] = si[t + o];
            }
        }
        __syncthreads();
    }
    int best = si[0];
    float* out = A + b * N;
    for (int i = t; i < N; i += 256) out[i] = (i == best) ? 1.0f : 0.0f;
}

// ---------------- hop-0 logit: gather C0 rows, dot with u ----------------
__global__ void k_logit_gather(const int* __restrict__ story,
                               const float* __restrict__ Ct)
{
    int gid  = blockIdx.x * blockDim.x + threadIdx.x;
    int warp = gid >> 5, lane = gid & 31;
    if (warp >= B * S) return;
    int b = warp >> 11;
    int4 idx = __ldg((const int4*)story + warp);
    float4 a = __ldg((const float4*)(Ct + (size_t)idx.x * E) + lane);
    float4 c = __ldg((const float4*)(Ct + (size_t)idx.y * E) + lane);
    float4 d = __ldg((const float4*)(Ct + (size_t)idx.z * E) + lane);
    float4 e = __ldg((const float4*)(Ct + (size_t)idx.w * E) + lane);
    float4 u4 = *((const float4*)(g_u + b * HH) + lane);
    float s = (a.x + c.x + d.x + e.x) * u4.x
            + (a.y + c.y + d.y + e.y) * u4.y
            + (a.z + c.z + d.z + e.z) * u4.z
            + (a.w + c.w + d.w + e.w) * u4.w;
    #pragma unroll
    for (int o = 16; o; o >>= 1) s += __shfl_down_sync(FULLMASK, s, o);
    if (lane == 0) g_logit[warp] = s;
}

// ---------------- logit from precomputed summed embeddings ----------------
__global__ void k_logit_seq(const float* __restrict__ emb)
{
    int gid  = blockIdx.x * blockDim.x + threadIdx.x;
    int warp = gid >> 5, lane = gid & 31;
    if (warp >= B * S) return;
    int b = warp >> 11;
    float4 e4 = __ldg((const float4*)(emb + (size_t)warp * E) + lane);
    float4 u4 = *((const float4*)(g_u + b * HH) + lane);
    float s = e4.x * u4.x + e4.y * u4.y + e4.z * u4.z + e4.w * u4.w;
    #pragma unroll
    for (int o = 16; o; o >>= 1) s += __shfl_down_sync(FULLMASK, s, o);
    if (lane == 0) g_logit[warp] = s;
}

// ---------------- final: logit from emb2, sigmoid + length mask -> out ----------------
__global__ void k_logit_mask(const float* __restrict__ emb,
                             const int* __restrict__ lengths,
                             float* __restrict__ out)
{
    int gid  = blockIdx.x * blockDim.x + threadIdx.x;
    int warp = gid >> 5, lane = gid & 31;
    if (warp >= B * S) return;
    int b = warp >> 11;
    float4 e4 = __ldg((const float4*)(emb + (size_t)warp * E) + lane);
    float4 u4 = *((const float4*)(g_u + b * HH) + lane);
    float s = e4.x * u4.x + e4.y * u4.y + e4.z * u4.z + e4.w * u4.w;
    #pragma unroll
    for (int o = 16; o; o >>= 1) s += __shfl_down_sync(FULLMASK, s, o);
    if (lane == 0) {
        int sl = warp & (S - 1);
        float v = 0.0f;
        if (sl < __ldg(lengths + b)) v = 1.0f / (1.0f + expf(-s));
        out[warp] = v;
    }
}

// ---------------- fused: softmax stats + gather Ct + emb write + u atomic update ----
// grid (32, B), 128 threads. Each block: redundant softmax stats over S, then
// 64 slots: gather+sum 4 rows, write summed embedding to scratch, accumulate p*v.
__global__ void k_update(const int* __restrict__ story,
                         const float* __restrict__ Ct,
                         float* __restrict__ emb_out)
{
    int b = blockIdx.y, chunk = blockIdx.x;
    int t = threadIdx.x;  // 128
    __shared__ float spb[S];   // exp(l - max)
    __shared__ float red[128];

    const float* l = g_logit + b * S;
    float m = -INFINITY;
    for (int i = t; i < S; i += 128) m = fmaxf(m, l[i]);
    red[t] = m; __syncthreads();
    for (int o = 64; o; o >>= 1) { if (t < o) red[t] = fmaxf(red[t], red[t + o]); __syncthreads(); }
    m = red[0]; __syncthreads();
    float sum = 0.f;
    for (int i = t; i < S; i += 128) { float e = expf(l[i] - m); spb[i] = e; sum += e; }
    red[t] = sum; __syncthreads();
    for (int o = 64; o; o >>= 1) { if (t < o) red[t] += red[t + o]; __syncthreads(); }
    float inv = 1.0f / red[0];
    __syncthreads();

    float acc = 0.f;
    int s0 = chunk * (S / 32);
    for (int s = s0; s < s0 + (S / 32); s += 2) {
        int4 i0 = __ldg((const int4*)story + b * S + s);
        int4 i1 = __ldg((const int4*)story + b * S + s + 1);
        float v0 = __ldg(Ct + (size_t)i0.x * E + t)
                 + __ldg(Ct + (size_t)i0.y * E + t)
                 + __ldg(Ct + (size_t)i0.z * E + t)
                 + __ldg(Ct + (size_t)i0.w * E + t);
        float v1 = __ldg(Ct + (size_t)i1.x * E + t)
                 + __ldg(Ct + (size_t)i1.y * E + t)
                 + __ldg(Ct + (size_t)i1.z * E + t)
                 + __ldg(Ct + (size_t)i1.w * E + t);
        emb_out[(size_t)(b * S + s) * E + t]     = v0;
        emb_out[(size_t)(b * S + s + 1) * E + t] = v1;
        acc = fmaf(spb[s] * inv, v0, acc);
        acc = fmaf(spb[s + 1] * inv, v1, acc);
    }
    atomicAdd(&g_u[b * HH + t], acc);
}

// ---------------- host launch ----------------
extern "C" void kernel_launch(void* const* d_in, const int* in_sizes, int n_in,
                              void* d_out, int out_size)
{
    const int*   story   = (const int*)d_in[0];
    const int*   lengths = (const int*)d_in[1];
    const float* hidden  = (const float*)d_in[2];
    // d_in[3] global_pointer: unused (is_decoding == 0 path)
    const float* C       = (const float*)d_in[4];
    const float* Wm      = (const float*)d_in[5];
    const float* Wb      = (const float*)d_in[6];
    const float* W1w     = (const float*)d_in[7];
    const float* W1b     = (const float*)d_in[8];
    const float* W3w     = (const float*)d_in[9];
    const float* W3b     = (const float*)d_in[10];
    const float* W4w     = (const float*)d_in[11];
    const float* W4b     = (const float*)d_in[12];

    float* out = (float*)d_out;
    float* o_sp   = out;                       // [B,2]
    float* o_spa  = out + B * 2;               // [B,2]
    float* o_qh   = out + B * 4;               // [B,4000]
    float* o_qha  = o_qh + B * NE;             // [B,4000]
    float* o_qt   = o_qha + B * NE;            // [B,200]
    float* o_qta  = o_qt + B * NR;             // [B,200]
    float* o_mask = o_qta + B * NR;            // [B,S]

    // JAX partitionable split of key(42): k_i = threefry(key, (0, i))
    uint32_t k1a, k1b, k2a, k2b, k3a, k3b;
    threefry2x32(0u, 42u, 0u, 0u, k1a, k1b);
    threefry2x32(0u, 42u, 0u, 1u, k2a, k2b);
    threefry2x32(0u, 42u, 0u, 2u, k3a, k3b);

    const size_t TBL = (size_t)VOCAB * E;

    k_h<<<B, HH>>>(hidden, Wm, Wb);

    // heads: one warp per column across all three heads
    {
        int warps  = 2 + NE + NR;
        int blocks = (warps * 32 + 255) / 256;
        k_head_all<<<blocks, 256>>>(W1w, W1b, W3w, W3b, W4w, W4b, o_sp, o_qh, o_qt);
        dim3 g(B, 3);
        k_argmax_all<<<g, 256>>>(o_sp, o_qh, o_qt, o_spa, o_qha, o_qta,
                                 k1a, k1b, k2a, k2b, k3a, k3b);
    }

    // hop 0: gather C0 for logits, then fused stats+gather C1 (writes emb1)
    k_logit_gather<<<(B * S * 32) / 256, 256>>>(story, C);
    {
        dim3 g(32, B);
        k_update<<<g, 128>>>(story, C + TBL, g_emb1);
    }
    // hop 1: logits from emb1, fused stats+gather C2 (writes emb2)
    k_logit_seq<<<(B * S * 32) / 256, 256>>>(g_emb1);
    {
        dim3 g(32, B);
        k_update<<<g, 128>>>(story, C + 2 * TBL, g_emb2);
    }
    // hop 2: logits from emb2 -> masked sigmoid, straight to output
    k_logit_mask<<<(B * S * 32) / 256, 256>>>(g_emb2, lengths, o_mask);
}

// round 3
// speedup vs baseline: 3.4821x; 3.4821x over previous
#include <cuda_runtime.h>
#include <math.h>
#include <stdint.h>

// Problem constants
#define B 16
#define S 2048
#define M 4
#define E 128
#define HH 128
#define VOCAB 100000
#define NE 4000
#define NR 200
#define FULLMASK 0xffffffffu

// ---------------- device scratch (no allocation allowed) ----------------
__device__ float g_h[B * HH];
__device__ float g_u[B * HH];
__device__ float g_logit[B * S];
__device__ float g_prob[B * S];

// ---------------- threefry2x32-20 (JAX) ----------------
__host__ __device__ __forceinline__ uint32_t rotl32(uint32_t v, int d) {
    return (v << d) | (v >> (32 - d));
}

__host__ __device__ __forceinline__ void threefry2x32(
    uint32_t k0, uint32_t k1, uint32_t x0, uint32_t x1,
    uint32_t& o0, uint32_t& o1)
{
    uint32_t ks0 = k0, ks1 = k1;
    uint32_t ks2 = k0 ^ k1 ^ 0x1BD11BDAu;
    x0 += ks0; x1 += ks1;
    const int rA[4] = {13, 15, 26, 6};
    const int rB[4] = {17, 29, 16, 24};
    #pragma unroll
    for (int i = 0; i < 4; i++) { x0 += x1; x1 = rotl32(x1, rA[i]); x1 ^= x0; }
    x0 += ks1; x1 += ks2 + 1u;
    #pragma unroll
    for (int i = 0; i < 4; i++) { x0 += x1; x1 = rotl32(x1, rB[i]); x1 ^= x0; }
    x0 += ks2; x1 += ks0 + 2u;
    #pragma unroll
    for (int i = 0; i < 4; i++) { x0 += x1; x1 = rotl32(x1, rA[i]); x1 ^= x0; }
    x0 += ks0; x1 += ks1 + 3u;
    #pragma unroll
    for (int i = 0; i < 4; i++) { x0 += x1; x1 = rotl32(x1, rB[i]); x1 ^= x0; }
    x0 += ks1; x1 += ks2 + 4u;
    #pragma unroll
    for (int i = 0; i < 4; i++) { x0 += x1; x1 = rotl32(x1, rA[i]); x1 ^= x0; }
    x0 += ks2; x1 += ks0 + 5u;
    o0 = x0; o1 = x1;
}

// ---------------- h = hidden @ Wm^T + Wb ; u = h ----------------
__global__ void k_h(const float* __restrict__ hidden,
                    const float* __restrict__ Wm,
                    const float* __restrict__ Wb)
{
    int b = blockIdx.x, t = threadIdx.x;
    __shared__ float sh[HH];
    sh[t] = hidden[b * HH + t];
    __syncthreads();
    float acc = Wb[t];
    const float* w = Wm + (size_t)t * HH;
    #pragma unroll 8
    for (int k = 0; k < HH; k++) acc = fmaf(w[k], sh[k], acc);
    g_h[b * HH + t] = acc;
    g_u[b * HH + t] = acc;
}

// ---------------- all three head GEMVs: warp per output column n ----------------
__global__ void k_head_all(const float* __restrict__ W1w, const float* __restrict__ W1b,
                           const float* __restrict__ W3w, const float* __restrict__ W3b,
                           const float* __restrict__ W4w, const float* __restrict__ W4b,
                           float* __restrict__ o_sp, float* __restrict__ o_qh,
                           float* __restrict__ o_qt)
{
    int gid  = blockIdx.x * blockDim.x + threadIdx.x;
    int w    = gid >> 5, lane = gid & 31;
    if (w >= 2 + NE + NR) return;
    const float *W, *bias; float* outl; int N, n;
    if (w < 2)            { W = W1w; bias = W1b; outl = o_sp; N = 2;  n = w; }
    else if (w < 2 + NE)  { W = W3w; bias = W3b; outl = o_qh; N = NE; n = w - 2; }
    else                  { W = W4w; bias = W4b; outl = o_qt; N = NR; n = w - 2 - NE; }

    float4 w4 = __ldg((const float4*)(W + (size_t)n * HH) + lane);
    float  bs = __ldg(bias + n);
    #pragma unroll
    for (int b = 0; b < B; b++) {
        float4 h4 = *((const float4*)(g_h + b * HH) + lane);
        float s = w4.x * h4.x + w4.y * h4.y + w4.z * h4.z + w4.w * h4.w;
        #pragma unroll
        for (int o = 16; o; o >>= 1) s += __shfl_down_sync(FULLMASK, s, o);
        if (lane == 0) outl[b * N + n] = s + bs;
    }
}

// ---------------- gumbel noise + argmax + one-hot, one block per (b, head) ----------------
__global__ void k_argmax_all(const float* __restrict__ o_sp, const float* __restrict__ o_qh,
                             const float* __restrict__ o_qt,
                             float* __restrict__ a_sp, float* __restrict__ a_qh,
                             float* __restrict__ a_qt,
                             uint32_t k1a, uint32_t k1b, uint32_t k2a, uint32_t k2b,
                             uint32_t k3a, uint32_t k3b)
{
    int b = blockIdx.x, head = blockIdx.y, t = threadIdx.x;
    const float* L; float* A; int N; uint32_t ka, kb;
    if (head == 0)      { L = o_sp; A = a_sp; N = 2;  ka = k1a; kb = k1b; }
    else if (head == 1) { L = o_qh; A = a_qh; N = NE; ka = k2a; kb = k2b; }
    else                { L = o_qt; A = a_qt; N = NR; ka = k3a; kb = k3b; }

    float bv = -INFINITY; int bi = 0x7fffffff;
    for (int i = t; i < N; i += 256) {
        int idx = b * N + i;
        float logit = __ldg(L + idx);
        uint32_t o0, o1;
        threefry2x32(ka, kb, 0u, (uint32_t)idx, o0, o1);
        uint32_t bits = o0 ^ o1;
        float u = __uint_as_float((bits >> 9) | 0x3F800000u) - 1.0f;
        float v = fmaxf(1e-10f, u + 1e-10f);
        float g = -logf(-logf(v));
        float nv = logit + g;
        if (nv > bv || (nv == bv && i < bi)) { bv = nv; bi = i; }
    }
    __shared__ float sv[256];
    __shared__ int   si[256];
    sv[t] = bv; si[t] = bi;
    __syncthreads();
    for (int o = 128; o; o >>= 1) {
        if (t < o) {
            if (sv[t + o] > sv[t] || (sv[t + o] == sv[t] && si[t + o] < si[t])) {
                sv[t] = sv[t + o]; si[t] = si[t + o];
            }
        }
        __syncthreads();
    }
    int best = si[0];
    float* out = A + b * N;
    for (int i = t; i < N; i += 256) out[i] = (i == best) ? 1.0f : 0.0f;
}

// ---------------- hop logit: 2 slots per warp for MLP ----------------
__global__ void k_hop_logit(const int* __restrict__ story,
                            const float* __restrict__ Ct)
{
    int gid  = blockIdx.x * blockDim.x + threadIdx.x;
    int warp = gid >> 5, lane = gid & 31;
    if (warp >= B * S / 2) return;
    int s0 = warp * 2;
    int b  = s0 >> 11;
    int4 ia = __ldg((const int4*)story + s0);
    int4 ib = __ldg((const int4*)story + s0 + 1);
    float4 a0 = __ldg((const float4*)(Ct + (size_t)ia.x * E) + lane);
    float4 a1 = __ldg((const float4*)(Ct + (size_t)ia.y * E) + lane);
    float4 a2 = __ldg((const float4*)(Ct + (size_t)ia.z * E) + lane);
    float4 a3 = __ldg((const float4*)(Ct + (size_t)ia.w * E) + lane);
    float4 b0 = __ldg((const float4*)(Ct + (size_t)ib.x * E) + lane);
    float4 b1 = __ldg((const float4*)(Ct + (size_t)ib.y * E) + lane);
    float4 b2 = __ldg((const float4*)(Ct + (size_t)ib.z * E) + lane);
    float4 b3 = __ldg((const float4*)(Ct + (size_t)ib.w * E) + lane);
    float4 u4 = *((const float4*)(g_u + b * HH) + lane);
    float sa = (a0.x + a1.x + a2.x + a3.x) * u4.x
             + (a0.y + a1.y + a2.y + a3.y) * u4.y
             + (a0.z + a1.z + a2.z + a3.z) * u4.z
             + (a0.w + a1.w + a2.w + a3.w) * u4.w;
    float sb = (b0.x + b1.x + b2.x + b3.x) * u4.x
             + (b0.y + b1.y + b2.y + b3.y) * u4.y
             + (b0.z + b1.z + b2.z + b3.z) * u4.z
             + (b0.w + b1.w + b2.w + b3.w) * u4.w;
    #pragma unroll
    for (int o = 16; o; o >>= 1) {
        sa += __shfl_down_sync(FULLMASK, sa, o);
        sb += __shfl_down_sync(FULLMASK, sb, o);
    }
    if (lane == 0) { g_logit[s0] = sa; g_logit[s0 + 1] = sb; }
}

// ---------------- final hop: logits -> sigmoid + length mask -> out ----------------
__global__ void k_hop_logit_mask(const int* __restrict__ story,
                                 const float* __restrict__ Ct,
                                 const int* __restrict__ lengths,
                                 float* __restrict__ out)
{
    int gid  = blockIdx.x * blockDim.x + threadIdx.x;
    int warp = gid >> 5, lane = gid & 31;
    if (warp >= B * S / 2) return;
    int s0 = warp * 2;
    int b  = s0 >> 11;
    int4 ia = __ldg((const int4*)story + s0);
    int4 ib = __ldg((const int4*)story + s0 + 1);
    float4 a0 = __ldg((const float4*)(Ct + (size_t)ia.x * E) + lane);
    float4 a1 = __ldg((const float4*)(Ct + (size_t)ia.y * E) + lane);
    float4 a2 = __ldg((const float4*)(Ct + (size_t)ia.z * E) + lane);
    float4 a3 = __ldg((const float4*)(Ct + (size_t)ia.w * E) + lane);
    float4 b0 = __ldg((const float4*)(Ct + (size_t)ib.x * E) + lane);
    float4 b1 = __ldg((const float4*)(Ct + (size_t)ib.y * E) + lane);
    float4 b2 = __ldg((const float4*)(Ct + (size_t)ib.z * E) + lane);
    float4 b3 = __ldg((const float4*)(Ct + (size_t)ib.w * E) + lane);
    float4 u4 = *((const float4*)(g_u + b * HH) + lane);
    float sa = (a0.x + a1.x + a2.x + a3.x) * u4.x
             + (a0.y + a1.y + a2.y + a3.y) * u4.y
             + (a0.z + a1.z + a2.z + a3.z) * u4.z
             + (a0.w + a1.w + a2.w + a3.w) * u4.w;
    float sb = (b0.x + b1.x + b2.x + b3.x) * u4.x
             + (b0.y + b1.y + b2.y + b3.y) * u4.y
             + (b0.z + b1.z + b2.z + b3.z) * u4.z
             + (b0.w + b1.w + b2.w + b3.w) * u4.w;
    #pragma unroll
    for (int o = 16; o; o >>= 1) {
        sa += __shfl_down_sync(FULLMASK, sa, o);
        sb += __shfl_down_sync(FULLMASK, sb, o);
    }
    if (lane == 0) {
        int len = __ldg(lengths + b);
        int sl = s0 & (S - 1);
        out[s0]     = (sl < len)     ? 1.0f / (1.0f + expf(-sa)) : 0.0f;
        out[s0 + 1] = (sl + 1 < len) ? 1.0f / (1.0f + expf(-sb)) : 0.0f;
    }
}

// ---------------- softmax over S per batch ----------------
__global__ void k_softmax()
{
    int b = blockIdx.x, t = threadIdx.x; // 256 threads
    const float* l = g_logit + b * S;
    float* p = g_prob + b * S;
    __shared__ float red[256];
    float m = -INFINITY;
    for (int i = t; i < S; i += 256) m = fmaxf(m, l[i]);
    red[t] = m; __syncthreads();
    for (int o = 128; o; o >>= 1) { if (t < o) red[t] = fmaxf(red[t], red[t + o]); __syncthreads(); }
    m = red[0]; __syncthreads();
    float sum = 0.f;
    for (int i = t; i < S; i += 256) { float e = expf(l[i] - m); p[i] = e; sum += e; }
    red[t] = sum; __syncthreads();
    for (int o = 128; o; o >>= 1) { if (t < o) red[t] += red[t + o]; __syncthreads(); }
    float inv = 1.0f / red[0];
    for (int i = t; i < S; i += 256) p[i] *= inv;
}

// ---------------- u update: acc_e = sum_s prob[b,s] * sum_m C[story]; atomic into g_u ----
__global__ void k_update(const int* __restrict__ story,
                         const float* __restrict__ Ct)
{
    int b = blockIdx.y, chunk = blockIdx.x;
    int e = threadIdx.x; // 128
    float acc = 0.f;
    int s0 = chunk * (S / 32);
    for (int s = s0; s < s0 + (S / 32); s++) {
        float p = g_prob[b * S + s];
        int4 idx = __ldg((const int4*)story + b * S + s);
        float v = __ldg(Ct + (size_t)idx.x * E + e)
                + __ldg(Ct + (size_t)idx.y * E + e)
                + __ldg(Ct + (size_t)idx.z * E + e)
                + __ldg(Ct + (size_t)idx.w * E + e);
        acc = fmaf(p, v, acc);
    }
    atomicAdd(&g_u[b * HH + e], acc);
}

// ---------------- host launch ----------------
extern "C" void kernel_launch(void* const* d_in, const int* in_sizes, int n_in,
                              void* d_out, int out_size)
{
    const int*   story   = (const int*)d_in[0];
    const int*   lengths = (const int*)d_in[1];
    const float* hidden  = (const float*)d_in[2];
    // d_in[3] global_pointer: unused (is_decoding == 0 path)
    const float* C       = (const float*)d_in[4];
    const float* Wm      = (const float*)d_in[5];
    const float* Wb      = (const float*)d_in[6];
    const float* W1w     = (const float*)d_in[7];
    const float* W1b     = (const float*)d_in[8];
    const float* W3w     = (const float*)d_in[9];
    const float* W3b     = (const float*)d_in[10];
    const float* W4w     = (const float*)d_in[11];
    const float* W4b     = (const float*)d_in[12];

    float* out = (float*)d_out;
    float* o_sp   = out;                       // [B,2]
    float* o_spa  = out + B * 2;               // [B,2]
    float* o_qh   = out + B * 4;               // [B,4000]
    float* o_qha  = o_qh + B * NE;             // [B,4000]
    float* o_qt   = o_qha + B * NE;            // [B,200]
    float* o_qta  = o_qt + B * NR;             // [B,200]
    float* o_mask = o_qta + B * NR;            // [B,S]

    // JAX partitionable split of key(42): k_i = threefry(key, (0, i))
    uint32_t k1a, k1b, k2a, k2b, k3a, k3b;
    threefry2x32(0u, 42u, 0u, 0u, k1a, k1b);
    threefry2x32(0u, 42u, 0u, 1u, k2a, k2b);
    threefry2x32(0u, 42u, 0u, 2u, k3a, k3b);

    const size_t TBL = (size_t)VOCAB * E;

    k_h<<<B, HH>>>(hidden, Wm, Wb);

    // heads
    {
        int warps  = 2 + NE + NR;
        int blocks = (warps * 32 + 255) / 256;
        k_head_all<<<blocks, 256>>>(W1w, W1b, W3w, W3b, W4w, W4b, o_sp, o_qh, o_qt);
        dim3 g(B, 3);
        k_argmax_all<<<g, 256>>>(o_sp, o_qh, o_qt, o_spa, o_qha, o_qta,
                                 k1a, k1b, k2a, k2b, k3a, k3b);
    }

    // memory hops: full pass for hop 0,1; hop 2 only needs the logits
    int lblocks = (B * S / 2 * 32) / 256;
    for (int hop = 0; hop < 2; hop++) {
        k_hop_logit<<<lblocks, 256>>>(story, C + (size_t)hop * TBL);
        k_softmax<<<B, 256>>>();
        dim3 g(32, B);
        k_update<<<g, 128>>>(story, C + (size_t)(hop + 1) * TBL);
    }
    k_hop_logit_mask<<<lblocks, 256>>>(story, C + (size_t)2 * TBL, lengths, o_mask);
}

// round 4
// speedup vs baseline: 4.9456x; 1.4203x over previous
#include <cuda_runtime.h>
#include <math.h>
#include <stdint.h>

// Problem constants
#define B 16
#define S 2048
#define M 4
#define E 128
#define HH 128
#define VOCAB 100000
#define NE 4000
#define NR 200
#define FULLMASK 0xffffffffu

// ---------------- device scratch (no allocation allowed) ----------------
__device__ float g_h[B * HH];
__device__ float g_u[B * HH];
__device__ float g_logit[B * S];

// ---------------- threefry2x32-20 (JAX) ----------------
__host__ __device__ __forceinline__ uint32_t rotl32(uint32_t v, int d) {
    return (v << d) | (v >> (32 - d));
}

__host__ __device__ __forceinline__ void threefry2x32(
    uint32_t k0, uint32_t k1, uint32_t x0, uint32_t x1,
    uint32_t& o0, uint32_t& o1)
{
    uint32_t ks0 = k0, ks1 = k1;
    uint32_t ks2 = k0 ^ k1 ^ 0x1BD11BDAu;
    x0 += ks0; x1 += ks1;
    const int rA[4] = {13, 15, 26, 6};
    const int rB[4] = {17, 29, 16, 24};
    #pragma unroll
    for (int i = 0; i < 4; i++) { x0 += x1; x1 = rotl32(x1, rA[i]); x1 ^= x0; }
    x0 += ks1; x1 += ks2 + 1u;
    #pragma unroll
    for (int i = 0; i < 4; i++) { x0 += x1; x1 = rotl32(x1, rB[i]); x1 ^= x0; }
    x0 += ks2; x1 += ks0 + 2u;
    #pragma unroll
    for (int i = 0; i < 4; i++) { x0 += x1; x1 = rotl32(x1, rA[i]); x1 ^= x0; }
    x0 += ks0; x1 += ks1 + 3u;
    #pragma unroll
    for (int i = 0; i < 4; i++) { x0 += x1; x1 = rotl32(x1, rB[i]); x1 ^= x0; }
    x0 += ks1; x1 += ks2 + 4u;
    #pragma unroll
    for (int i = 0; i < 4; i++) { x0 += x1; x1 = rotl32(x1, rA[i]); x1 ^= x0; }
    x0 += ks2; x1 += ks0 + 5u;
    o0 = x0; o1 = x1;
}

// ---------------- h = hidden @ Wm^T + Wb ; u = h ----------------
__global__ void k_h(const float* __restrict__ hidden,
                    const float* __restrict__ Wm,
                    const float* __restrict__ Wb)
{
    int b = blockIdx.x, t = threadIdx.x;
    __shared__ float sh[HH];
    sh[t] = hidden[b * HH + t];
    __syncthreads();
    float acc = Wb[t];
    const float* w = Wm + (size_t)t * HH;
    #pragma unroll 8
    for (int k = 0; k < HH; k++) acc = fmaf(w[k], sh[k], acc);
    g_h[b * HH + t] = acc;
    g_u[b * HH + t] = acc;
}

// ---------------- all three head GEMVs: warp per output column n ----------------
__global__ void k_head_all(const float* __restrict__ W1w, const float* __restrict__ W1b,
                           const float* __restrict__ W3w, const float* __restrict__ W3b,
                           const float* __restrict__ W4w, const float* __restrict__ W4b,
                           float* __restrict__ o_sp, float* __restrict__ o_qh,
                           float* __restrict__ o_qt)
{
    int gid  = blockIdx.x * blockDim.x + threadIdx.x;
    int w    = gid >> 5, lane = gid & 31;
    if (w >= 2 + NE + NR) return;
    const float *W, *bias; float* outl; int N, n;
    if (w < 2)            { W = W1w; bias = W1b; outl = o_sp; N = 2;  n = w; }
    else if (w < 2 + NE)  { W = W3w; bias = W3b; outl = o_qh; N = NE; n = w - 2; }
    else                  { W = W4w; bias = W4b; outl = o_qt; N = NR; n = w - 2 - NE; }

    float4 w4 = __ldg((const float4*)(W + (size_t)n * HH) + lane);
    float  bs = __ldg(bias + n);
    #pragma unroll
    for (int b = 0; b < B; b++) {
        float4 h4 = *((const float4*)(g_h + b * HH) + lane);
        float s = w4.x * h4.x + w4.y * h4.y + w4.z * h4.z + w4.w * h4.w;
        #pragma unroll
        for (int o = 16; o; o >>= 1) s += __shfl_down_sync(FULLMASK, s, o);
        if (lane == 0) outl[b * N + n] = s + bs;
    }
}

// ---------------- gumbel noise + argmax + one-hot, one block per (b, head) ----------------
__global__ void k_argmax_all(const float* __restrict__ o_sp, const float* __restrict__ o_qh,
                             const float* __restrict__ o_qt,
                             float* __restrict__ a_sp, float* __restrict__ a_qh,
                             float* __restrict__ a_qt,
                             uint32_t k1a, uint32_t k1b, uint32_t k2a, uint32_t k2b,
                             uint32_t k3a, uint32_t k3b)
{
    int b = blockIdx.x, head = blockIdx.y, t = threadIdx.x;
    const float* L; float* A; int N; uint32_t ka, kb;
    if (head == 0)      { L = o_sp; A = a_sp; N = 2;  ka = k1a; kb = k1b; }
    else if (head == 1) { L = o_qh; A = a_qh; N = NE; ka = k2a; kb = k2b; }
    else                { L = o_qt; A = a_qt; N = NR; ka = k3a; kb = k3b; }

    float bv = -INFINITY; int bi = 0x7fffffff;
    for (int i = t; i < N; i += 256) {
        int idx = b * N + i;
        float logit = __ldg(L + idx);
        uint32_t o0, o1;
        threefry2x32(ka, kb, 0u, (uint32_t)idx, o0, o1);
        uint32_t bits = o0 ^ o1;
        float u = __uint_as_float((bits >> 9) | 0x3F800000u) - 1.0f;
        float v = fmaxf(1e-10f, u + 1e-10f);
        float g = -logf(-logf(v));
        float nv = logit + g;
        if (nv > bv || (nv == bv && i < bi)) { bv = nv; bi = i; }
    }
    __shared__ float sv[256];
    __shared__ int   si[256];
    sv[t] = bv; si[t] = bi;
    __syncthreads();
    for (int o = 128; o; o >>= 1) {
        if (t < o) {
            if (sv[t + o] > sv[t] || (sv[t + o] == sv[t] && si[t + o] < si[t])) {
                sv[t] = sv[t + o]; si[t] = si[t + o];
            }
        }
        __syncthreads();
    }
    int best = si[0];
    float* out = A + b * N;
    for (int i = t; i < N; i += 256) out[i] = (i == best) ? 1.0f : 0.0f;
}

// ---------------- hop logit: 2 slots per warp for MLP ----------------
__global__ void k_hop_logit(const int* __restrict__ story,
                            const float* __restrict__ Ct)
{
    int gid  = blockIdx.x * blockDim.x + threadIdx.x;
    int warp = gid >> 5, lane = gid & 31;
    if (warp >= B * S / 2) return;
    int s0 = warp * 2;
    int b  = s0 >> 11;
    int4 ia = __ldg((const int4*)story + s0);
    int4 ib = __ldg((const int4*)story + s0 + 1);
    float4 a0 = __ldg((const float4*)(Ct + (size_t)ia.x * E) + lane);
    float4 a1 = __ldg((const float4*)(Ct + (size_t)ia.y * E) + lane);
    float4 a2 = __ldg((const float4*)(Ct + (size_t)ia.z * E) + lane);
    float4 a3 = __ldg((const float4*)(Ct + (size_t)ia.w * E) + lane);
    float4 b0 = __ldg((const float4*)(Ct + (size_t)ib.x * E) + lane);
    float4 b1 = __ldg((const float4*)(Ct + (size_t)ib.y * E) + lane);
    float4 b2 = __ldg((const float4*)(Ct + (size_t)ib.z * E) + lane);
    float4 b3 = __ldg((const float4*)(Ct + (size_t)ib.w * E) + lane);
    float4 u4 = *((const float4*)(g_u + b * HH) + lane);
    float sa = (a0.x + a1.x + a2.x + a3.x) * u4.x
             + (a0.y + a1.y + a2.y + a3.y) * u4.y
             + (a0.z + a1.z + a2.z + a3.z) * u4.z
             + (a0.w + a1.w + a2.w + a3.w) * u4.w;
    float sb = (b0.x + b1.x + b2.x + b3.x) * u4.x
             + (b0.y + b1.y + b2.y + b3.y) * u4.y
             + (b0.z + b1.z + b2.z + b3.z) * u4.z
             + (b0.w + b1.w + b2.w + b3.w) * u4.w;
    #pragma unroll
    for (int o = 16; o; o >>= 1) {
        sa += __shfl_down_sync(FULLMASK, sa, o);
        sb += __shfl_down_sync(FULLMASK, sb, o);
    }
    if (lane == 0) { g_logit[s0] = sa; g_logit[s0 + 1] = sb; }
}

// ---------------- final hop: logits -> sigmoid + length mask -> out ----------------
__global__ void k_hop_logit_mask(const int* __restrict__ story,
                                 const float* __restrict__ Ct,
                                 const int* __restrict__ lengths,
                                 float* __restrict__ out)
{
    int gid  = blockIdx.x * blockDim.x + threadIdx.x;
    int warp = gid >> 5, lane = gid & 31;
    if (warp >= B * S / 2) return;
    int s0 = warp * 2;
    int b  = s0 >> 11;
    int4 ia = __ldg((const int4*)story + s0);
    int4 ib = __ldg((const int4*)story + s0 + 1);
    float4 a0 = __ldg((const float4*)(Ct + (size_t)ia.x * E) + lane);
    float4 a1 = __ldg((const float4*)(Ct + (size_t)ia.y * E) + lane);
    float4 a2 = __ldg((const float4*)(Ct + (size_t)ia.z * E) + lane);
    float4 a3 = __ldg((const float4*)(Ct + (size_t)ia.w * E) + lane);
    float4 b0 = __ldg((const float4*)(Ct + (size_t)ib.x * E) + lane);
    float4 b1 = __ldg((const float4*)(Ct + (size_t)ib.y * E) + lane);
    float4 b2 = __ldg((const float4*)(Ct + (size_t)ib.z * E) + lane);
    float4 b3 = __ldg((const float4*)(Ct + (size_t)ib.w * E) + lane);
    float4 u4 = *((const float4*)(g_u + b * HH) + lane);
    float sa = (a0.x + a1.x + a2.x + a3.x) * u4.x
             + (a0.y + a1.y + a2.y + a3.y) * u4.y
             + (a0.z + a1.z + a2.z + a3.z) * u4.z
             + (a0.w + a1.w + a2.w + a3.w) * u4.w;
    float sb = (b0.x + b1.x + b2.x + b3.x) * u4.x
             + (b0.y + b1.y + b2.y + b3.y) * u4.y
             + (b0.z + b1.z + b2.z + b3.z) * u4.z
             + (b0.w + b1.w + b2.w + b3.w) * u4.w;
    #pragma unroll
    for (int o = 16; o; o >>= 1) {
        sa += __shfl_down_sync(FULLMASK, sa, o);
        sb += __shfl_down_sync(FULLMASK, sb, o);
    }
    if (lane == 0) {
        int len = __ldg(lengths + b);
        int sl = s0 & (S - 1);
        out[s0]     = (sl < len)     ? 1.0f / (1.0f + expf(-sa)) : 0.0f;
        out[s0 + 1] = (sl + 1 < len) ? 1.0f / (1.0f + expf(-sb)) : 0.0f;
    }
}

// ---------------- fused softmax + u update ----------------
// 256 blocks (16 per batch), 256 threads = 8 warps, 128 slots per block,
// 16 slots per warp. Block-redundant softmax stats (scalars only), warp-per-slot
// float4 gathers, smem cross-warp reduction, one atomicAdd per element per block.
__global__ void k_update(const int* __restrict__ story,
                         const float* __restrict__ Ct)
{
    int blk = blockIdx.x;
    int b   = blk >> 4;                 // 16 blocks per batch
    int slot0 = (blk & 15) * 128;
    int t = threadIdx.x, lane = t & 31, w = t >> 5;

    // softmax stats over the full row (scalars only)
    const float* l = g_logit + b * S;
    __shared__ float red[256];
    float m = -INFINITY;
    for (int i = t; i < S; i += 256) m = fmaxf(m, __ldg(l + i));
    red[t] = m; __syncthreads();
    #pragma unroll
    for (int o = 128; o; o >>= 1) { if (t < o) red[t] = fmaxf(red[t], red[t + o]); __syncthreads(); }
    m = red[0]; __syncthreads();
    float sum = 0.f;
    for (int i = t; i < S; i += 256) sum += expf(__ldg(l + i) - m);
    red[t] = sum; __syncthreads();
    #pragma unroll
    for (int o = 128; o; o >>= 1) { if (t < o) red[t] += red[t + o]; __syncthreads(); }
    float inv = 1.0f / red[0];
    __syncthreads();

    // gather: warp w handles slots [slot0 + w*16, +16), 2 per iteration
    float4 acc = make_float4(0.f, 0.f, 0.f, 0.f);
    int sbase = b * S + slot0 + w * 16;
    #pragma unroll 1
    for (int i = 0; i < 16; i += 2) {
        int s0 = sbase + i, s1 = s0 + 1;
        int4 i0 = __ldg((const int4*)story + s0);
        int4 i1 = __ldg((const int4*)story + s1);
        float p0 = expf(__ldg(g_logit + s0) - m) * inv;
        float p1 = expf(__ldg(g_logit + s1) - m) * inv;
        float4 a0 = __ldg((const float4*)(Ct + (size_t)i0.x * E) + lane);
        float4 a1 = __ldg((const float4*)(Ct + (size_t)i0.y * E) + lane);
        float4 a2 = __ldg((const float4*)(Ct + (size_t)i0.z * E) + lane);
        float4 a3 = __ldg((const float4*)(Ct + (size_t)i0.w * E) + lane);
        float4 c0 = __ldg((const float4*)(Ct + (size_t)i1.x * E) + lane);
        float4 c1 = __ldg((const float4*)(Ct + (size_t)i1.y * E) + lane);
        float4 c2 = __ldg((const float4*)(Ct + (size_t)i1.z * E) + lane);
        float4 c3 = __ldg((const float4*)(Ct + (size_t)i1.w * E) + lane);
        acc.x = fmaf(p0, a0.x + a1.x + a2.x + a3.x, acc.x);
        acc.y = fmaf(p0, a0.y + a1.y + a2.y + a3.y, acc.y);
        acc.z = fmaf(p0, a0.z + a1.z + a2.z + a3.z, acc.z);
        acc.w = fmaf(p0, a0.w + a1.w + a2.w + a3.w, acc.w);
        acc.x = fmaf(p1, c0.x + c1.x + c2.x + c3.x, acc.x);
        acc.y = fmaf(p1, c0.y + c1.y + c2.y + c3.y, acc.y);
        acc.z = fmaf(p1, c0.z + c1.z + c2.z + c3.z, acc.z);
        acc.w = fmaf(p1, c0.w + c1.w + c2.w + c3.w, acc.w);
    }

    // cross-warp reduce: 8 warps x 128 floats
    __shared__ float sred[8][128];
    *((float4*)&sred[w][lane * 4]) = acc;
    __syncthreads();
    if (t < 128) {
        float v = sred[0][t];
        #pragma unroll
        for (int ww = 1; ww < 8; ww++) v += sred[ww][t];
        atomicAdd(&g_u[b * HH + t], v);
    }
}

// ---------------- host launch ----------------
extern "C" void kernel_launch(void* const* d_in, const int* in_sizes, int n_in,
                              void* d_out, int out_size)
{
    const int*   story   = (const int*)d_in[0];
    const int*   lengths = (const int*)d_in[1];
    const float* hidden  = (const float*)d_in[2];
    // d_in[3] global_pointer: unused (is_decoding == 0 path)
    const float* C       = (const float*)d_in[4];
    const float* Wm      = (const float*)d_in[5];
    const float* Wb      = (const float*)d_in[6];
    const float* W1w     = (const float*)d_in[7];
    const float* W1b     = (const float*)d_in[8];
    const float* W3w     = (const float*)d_in[9];
    const float* W3b     = (const float*)d_in[10];
    const float* W4w     = (const float*)d_in[11];
    const float* W4b     = (const float*)d_in[12];

    float* out = (float*)d_out;
    float* o_sp   = out;                       // [B,2]
    float* o_spa  = out + B * 2;               // [B,2]
    float* o_qh   = out + B * 4;               // [B,4000]
    float* o_qha  = o_qh + B * NE;             // [B,4000]
    float* o_qt   = o_qha + B * NE;            // [B,200]
    float* o_qta  = o_qt + B * NR;             // [B,200]
    float* o_mask = o_qta + B * NR;            // [B,S]

    // JAX partitionable split of key(42): k_i = threefry(key, (0, i))
    uint32_t k1a, k1b, k2a, k2b, k3a, k3b;
    threefry2x32(0u, 42u, 0u, 0u, k1a, k1b);
    threefry2x32(0u, 42u, 0u, 1u, k2a, k2b);
    threefry2x32(0u, 42u, 0u, 2u, k3a, k3b);

    const size_t TBL = (size_t)VOCAB * E;

    k_h<<<B, HH>>>(hidden, Wm, Wb);

    // heads
    {
        int warps  = 2 + NE + NR;
        int blocks = (warps * 32 + 255) / 256;
        k_head_all<<<blocks, 256>>>(W1w, W1b, W3w, W3b, W4w, W4b, o_sp, o_qh, o_qt);
        dim3 g(B, 3);
        k_argmax_all<<<g, 256>>>(o_sp, o_qh, o_qt, o_spa, o_qha, o_qta,
                                 k1a, k1b, k2a, k2b, k3a, k3b);
    }

    // memory hops: full pass for hop 0,1; hop 2 only needs the logits
    int lblocks = (B * S / 2 * 32) / 256;
    for (int hop = 0; hop < 2; hop++) {
        k_hop_logit<<<lblocks, 256>>>(story, C + (size_t)hop * TBL);
        k_update<<<B * S / 128, 256>>>(story, C + (size_t)(hop + 1) * TBL);
    }
    k_hop_logit_mask<<<lblocks, 256>>>(story, C + (size_t)2 * TBL, lengths, o_mask);
}